// round 1
// baseline (speedup 1.0000x reference)
#include <cuda_runtime.h>
#include <math.h>

#define BS   16
#define NP   4000
#define CC   80
#define GG   300
#define KTOP 13
#define NTHREADS 256

// Scratch (device globals — no allocation allowed)
__device__ float g_scores_t[BS * CC * NP];            // sigmoid(logits) transposed to [b][c][n]
__device__ unsigned long long g_key[BS * NP];         // packed (mapped_overlap, ~g) per pred

struct Box { float x1, y1, x2, y2, area; };

__device__ __forceinline__ Box toxyxy(float4 b) {
    Box r;
    r.x1 = b.x - 0.5f * b.z;
    r.y1 = b.y - 0.5f * b.w;
    r.x2 = b.x + 0.5f * b.z;
    r.y2 = b.y + 0.5f * b.w;
    r.area = (r.x2 - r.x1) * (r.y2 - r.y1);
    return r;
}

__device__ __forceinline__ float neg_giou(const Box& a, const Box& b) {
    float ltx = fmaxf(a.x1, b.x1), lty = fmaxf(a.y1, b.y1);
    float rbx = fminf(a.x2, b.x2), rby = fminf(a.y2, b.y2);
    float wi = fmaxf(rbx - ltx, 0.f), hi = fmaxf(rby - lty, 0.f);
    float inter = wi * hi;
    float uni = a.area + b.area - inter;
    float iou = inter / uni;
    float lex = fminf(a.x1, b.x1), ley = fminf(a.y1, b.y1);
    float rex = fmaxf(a.x2, b.x2), rey = fmaxf(a.y2, b.y2);
    float we = fmaxf(rex - lex, 0.f), he = fmaxf(rey - ley, 0.f);
    float ae = we * he;
    float giou = iou - (ae - uni) / ae;
    return -giou;
}

__device__ __forceinline__ float pow6(float x) {
    float x2 = x * x;
    return x2 * x2 * x2;
}

// ---------------------------------------------------------------------------
// Kernel 1: sigmoid + transpose logits [b][n][c] -> scores_t [b][c][n]
// Tiled 32x32 through smem; both gmem sides coalesced.
// grid (NP/32, ceil(CC/32), BS), block (32, 8)
// ---------------------------------------------------------------------------
__global__ void sig_transpose_kernel(const float* __restrict__ logits) {
    __shared__ float tile[32][33];
    int b = blockIdx.z;
    int n0 = blockIdx.x * 32, c0 = blockIdx.y * 32;
    int tx = threadIdx.x, ty = threadIdx.y;
#pragma unroll
    for (int i = 0; i < 4; i++) {
        int c = c0 + tx;
        int n = n0 + ty + i * 8;
        float v = 0.f;
        if (c < CC) v = logits[((size_t)b * NP + n) * CC + c];
        tile[ty + i * 8][tx] = 1.f / (1.f + expf(-v));
    }
    __syncthreads();
#pragma unroll
    for (int i = 0; i < 4; i++) {
        int n = n0 + tx;
        int c = c0 + ty + i * 8;
        if (c < CC) g_scores_t[((size_t)b * CC + c) * NP + n] = tile[tx][ty + i * 8];
    }
}

// ---------------------------------------------------------------------------
// Kernel 2: zero the per-pred keys (runs every graph replay)
// ---------------------------------------------------------------------------
__global__ void init_key_kernel() {
    int i = blockIdx.x * blockDim.x + threadIdx.x;
    if (i < BS * NP) g_key[i] = 0ull;
}

// ---------------------------------------------------------------------------
// Kernel 3: per-(b,g) block — compute all N alignments, select top-13 positive,
// scatter (overlap, g) into g_key via atomicMax with first-index tiebreak.
// grid BS*GG, block 256
// ---------------------------------------------------------------------------
__global__ void __launch_bounds__(NTHREADS) assign_kernel(
    const float4* __restrict__ pred_boxes,
    const float4* __restrict__ gt_boxes,
    const int* __restrict__ gt_labels)
{
    __shared__ float s_align[NP];
    __shared__ float s_ov[NP];
    __shared__ float s_wv[8];
    __shared__ int   s_wi[8];
    __shared__ int   s_stop;

    int b = blockIdx.x / GG;
    int g = blockIdx.x - b * GG;
    int tid = threadIdx.x;

    Box gb = toxyxy(gt_boxes[b * GG + g]);
    int label = gt_labels[b * GG + g];
    const float*  srow = g_scores_t + ((size_t)b * CC + label) * NP;
    const float4* pb   = pred_boxes + (size_t)b * NP;

    for (int n = tid; n < NP; n += NTHREADS) {
        Box p = toxyxy(pb[n]);
        float ov = neg_giou(p, gb);
        float al = srow[n] * pow6(ov);
        s_ov[n] = ov;
        s_align[n] = al;
    }
    if (tid == 0) s_stop = 0;
    __syncthreads();

    unsigned long long* keyb = g_key + (size_t)b * NP;

    for (int k = 0; k < KTOP; k++) {
        // per-thread scan (strict > keeps smallest local index on ties)
        float bv = -1e30f;
        int bi = 0x7fffffff;
        for (int n = tid; n < NP; n += NTHREADS) {
            float v = s_align[n];
            if (v > bv) { bv = v; bi = n; }
        }
        // warp reduce: higher value wins; equal value -> smaller index
#pragma unroll
        for (int off = 16; off; off >>= 1) {
            float ov_ = __shfl_down_sync(0xffffffffu, bv, off);
            int   oi  = __shfl_down_sync(0xffffffffu, bi, off);
            if (ov_ > bv || (ov_ == bv && oi < bi)) { bv = ov_; bi = oi; }
        }
        if ((tid & 31) == 0) { s_wv[tid >> 5] = bv; s_wi[tid >> 5] = bi; }
        __syncthreads();
        if (tid < 32) {
            float v2 = (tid < 8) ? s_wv[tid] : -1e30f;
            int   i2 = (tid < 8) ? s_wi[tid] : 0x7fffffff;
#pragma unroll
            for (int off = 4; off; off >>= 1) {
                float ov_ = __shfl_down_sync(0xffffffffu, v2, off);
                int   oi  = __shfl_down_sync(0xffffffffu, i2, off);
                if (ov_ > v2 || (ov_ == v2 && oi < i2)) { v2 = ov_; i2 = oi; }
            }
            if (tid == 0) {
                if (v2 <= 0.f) {
                    s_stop = 1;
                } else {
                    float ov = s_ov[i2];
                    unsigned int u = __float_as_uint(ov);
                    unsigned int m = (u & 0x80000000u) ? ~u : (u | 0x80000000u);
                    unsigned long long key =
                        ((unsigned long long)m << 32) | (unsigned long long)(0xffffffffu - (unsigned)g);
                    atomicMax(keyb + i2, key);
                    s_align[i2] = -1e30f;   // exclude from subsequent rounds
                }
            }
        }
        __syncthreads();
        if (s_stop) break;
    }
}

// ---------------------------------------------------------------------------
// Kernel 4: finalize — decode winner per pred, recompute alignment metric.
// ---------------------------------------------------------------------------
__global__ void finalize_kernel(
    const float4* __restrict__ pred_boxes,
    const float4* __restrict__ gt_boxes,
    const int* __restrict__ gt_labels,
    float* __restrict__ out)
{
    int i = blockIdx.x * blockDim.x + threadIdx.x;
    if (i >= BS * NP) return;
    int b = i / NP;
    int n = i - b * NP;

    unsigned long long key = g_key[i];
    float inds = 0.f, lab = -1.f, met = 0.f;
    if (key != 0ull) {
        int g = (int)(0xffffffffu - (unsigned)(key & 0xffffffffu));
        Box p  = toxyxy(pred_boxes[(size_t)b * NP + n]);
        Box gb = toxyxy(gt_boxes[b * GG + g]);
        float ov = neg_giou(p, gb);
        int label = gt_labels[b * GG + g];
        float s = g_scores_t[((size_t)b * CC + label) * NP + n];
        met = s * pow6(ov);
        inds = (float)(g + 1);
        lab = (float)label;
    }
    out[i] = inds;
    out[BS * NP + i] = lab;
    out[2 * BS * NP + i] = met;
}

// ---------------------------------------------------------------------------
extern "C" void kernel_launch(void* const* d_in, const int* in_sizes, int n_in,
                              void* d_out, int out_size) {
    const float*  logits     = (const float*)d_in[0];
    const float4* pred_boxes = (const float4*)d_in[1];
    const float4* gt_boxes   = (const float4*)d_in[2];
    const int*    gt_labels  = (const int*)d_in[3];
    float* out = (float*)d_out;

    dim3 tgrid(NP / 32, (CC + 31) / 32, BS);
    sig_transpose_kernel<<<tgrid, dim3(32, 8)>>>(logits);
    init_key_kernel<<<(BS * NP + 255) / 256, 256>>>();
    assign_kernel<<<BS * GG, NTHREADS>>>(pred_boxes, gt_boxes, gt_labels);
    finalize_kernel<<<(BS * NP + 255) / 256, 256>>>(pred_boxes, gt_boxes, gt_labels, out);
}

// round 2
// speedup vs baseline: 1.2785x; 1.2785x over previous
#include <cuda_runtime.h>
#include <math.h>

#define BS   16
#define NP   4000
#define CC   80
#define GG   300
#define KTOP 13
#define NTH  128
#define PT   32          // elements per thread (128*32 = 4096 >= 4000)

// Scratch (device globals — no allocation allowed; zero-initialized at load)
__device__ float g_scores_t[BS * CC * NP];       // sigmoid(logits) transposed [b][c][n]
__device__ unsigned long long g_key[BS * NP];    // packed (mapped_overlap, ~g) per pred

struct Box { float x1, y1, x2, y2, area; };

__device__ __forceinline__ Box toxyxy(float4 b) {
    Box r;
    r.x1 = b.x - 0.5f * b.z;
    r.y1 = b.y - 0.5f * b.w;
    r.x2 = b.x + 0.5f * b.z;
    r.y2 = b.y + 0.5f * b.w;
    r.area = (r.x2 - r.x1) * (r.y2 - r.y1);
    return r;
}

__device__ __forceinline__ float neg_giou(const Box& a, const Box& b) {
    float ltx = fmaxf(a.x1, b.x1), lty = fmaxf(a.y1, b.y1);
    float rbx = fminf(a.x2, b.x2), rby = fminf(a.y2, b.y2);
    float wi = fmaxf(rbx - ltx, 0.f), hi = fmaxf(rby - lty, 0.f);
    float inter = wi * hi;
    float uni = a.area + b.area - inter;
    float iou = inter / uni;
    float lex = fminf(a.x1, b.x1), ley = fminf(a.y1, b.y1);
    float rex = fmaxf(a.x2, b.x2), rey = fmaxf(a.y2, b.y2);
    float we = fmaxf(rex - lex, 0.f), he = fmaxf(rey - ley, 0.f);
    float ae = we * he;
    float giou = iou - (ae - uni) / ae;
    return -giou;
}

__device__ __forceinline__ float pow6(float x) {
    float x2 = x * x;
    return x2 * x2 * x2;
}

// monotone map: float -> u32 preserving order as unsigned
__device__ __forceinline__ unsigned int fmap(float f) {
    unsigned int u = __float_as_uint(f);
    return (u & 0x80000000u) ? ~u : (u | 0x80000000u);
}

__device__ __forceinline__ unsigned long long pack_key(float v, int idx) {
    return ((unsigned long long)fmap(v) << 32) |
           (unsigned long long)(0xffffffffu - (unsigned)idx);
}

// ---------------------------------------------------------------------------
// Kernel 1: sigmoid + transpose logits [b][n][c] -> scores_t [b][c][n]
// ---------------------------------------------------------------------------
__global__ void sig_transpose_kernel(const float* __restrict__ logits) {
    __shared__ float tile[32][33];
    int b = blockIdx.z;
    int n0 = blockIdx.x * 32, c0 = blockIdx.y * 32;
    int tx = threadIdx.x, ty = threadIdx.y;
#pragma unroll
    for (int i = 0; i < 4; i++) {
        int c = c0 + tx;
        int n = n0 + ty + i * 8;
        float v = 0.f;
        if (c < CC) v = logits[((size_t)b * NP + n) * CC + c];
        tile[ty + i * 8][tx] = 1.f / (1.f + expf(-v));
    }
    __syncthreads();
#pragma unroll
    for (int i = 0; i < 4; i++) {
        int n = n0 + tx;
        int c = c0 + ty + i * 8;
        if (c < CC) g_scores_t[((size_t)b * CC + c) * NP + n] = tile[tx][ty + i * 8];
    }
}

// ---------------------------------------------------------------------------
// Kernel 2: per-(b,g) block — compute alignments, iterative top-13 via
// register-cached per-thread candidates; scatter winners via atomicMax.
// grid BS*GG, block 128, smem 16KB (s_align only)
// ---------------------------------------------------------------------------
__global__ void __launch_bounds__(NTH) assign_kernel(
    const float4* __restrict__ pred_boxes,
    const float4* __restrict__ gt_boxes,
    const int* __restrict__ gt_labels)
{
    __shared__ float s_align[NP];
    __shared__ unsigned long long s_lead[NTH / 32];
    __shared__ unsigned long long s_win;

    int b = blockIdx.x / GG;
    int g = blockIdx.x - b * GG;
    int tid = threadIdx.x;
    int wid = tid >> 5, lane = tid & 31;

    Box gb = toxyxy(gt_boxes[b * GG + g]);
    int label = gt_labels[b * GG + g];
    const float*  srow = g_scores_t + ((size_t)b * CC + label) * NP;
    const float4* pb   = pred_boxes + (size_t)b * NP;

    // Compute phase: fill s_align, track per-thread best in registers
    float bv = -2.0f;    // all real alignments are >= 0
    int   bi = 0x7fffffff;
#pragma unroll 4
    for (int j = 0; j < PT; j++) {
        int n = tid + j * NTH;
        if (n < NP) {
            Box p = toxyxy(pb[n]);
            float ov = neg_giou(p, gb);
            float al = srow[n] * pow6(ov);
            s_align[n] = al;
            if (al > bv) { bv = al; bi = n; }   // ascending n -> smallest idx on tie
        }
    }
    unsigned long long ckey = pack_key(bv, bi);
    __syncthreads();

    unsigned long long* keyb = g_key + (size_t)b * NP;

    for (int k = 0; k < KTOP; k++) {
        // warp max-reduce of packed keys
        unsigned long long wk = ckey;
#pragma unroll
        for (int off = 16; off; off >>= 1) {
            unsigned long long o = __shfl_down_sync(0xffffffffu, wk, off);
            if (o > wk) wk = o;
        }
        if (lane == 0) s_lead[wid] = wk;
        __syncthreads();                    // (A)
        if (tid == 0) {
            unsigned long long w = s_lead[0];
#pragma unroll
            for (int i = 1; i < NTH / 32; i++)
                if (s_lead[i] > w) w = s_lead[i];
            s_win = w;
        }
        __syncthreads();                    // (B)
        unsigned long long w = s_win;

        // stop when best alignment <= 0 (mapped(0.0f) == 0x80000000)
        if ((unsigned int)(w >> 32) <= 0x80000000u) break;

        int idx = (int)(0xffffffffu - (unsigned int)w);
        if ((idx & (NTH - 1)) == tid) {
            // I own the winning element: emit it, then refresh my candidate
            Box p = toxyxy(pb[idx]);
            float ov = neg_giou(p, gb);
            unsigned long long key = pack_key(ov, g);   // fmap handles sign; ~g tiebreak
            atomicMax(keyb + idx, key);

            s_align[idx] = -1.0f;
            float nbv = -2.0f; int nbi = 0x7fffffff;
#pragma unroll 4
            for (int j = 0; j < PT; j++) {
                int n = tid + j * NTH;
                if (n < NP) {
                    float v = s_align[n];
                    if (v > nbv) { nbv = v; nbi = n; }
                }
            }
            ckey = pack_key(nbv, nbi);
        }
    }
}

// ---------------------------------------------------------------------------
// Kernel 3: finalize — decode winner per pred, recompute metric, reset key.
// ---------------------------------------------------------------------------
__global__ void finalize_kernel(
    const float4* __restrict__ pred_boxes,
    const float4* __restrict__ gt_boxes,
    const int* __restrict__ gt_labels,
    float* __restrict__ out)
{
    int i = blockIdx.x * blockDim.x + threadIdx.x;
    if (i >= BS * NP) return;
    int b = i / NP;
    int n = i - b * NP;

    unsigned long long key = g_key[i];
    g_key[i] = 0ull;    // reset for next graph replay
    float inds = 0.f, lab = -1.f, met = 0.f;
    if (key != 0ull) {
        int g = (int)(0xffffffffu - (unsigned)(key & 0xffffffffu));
        Box p  = toxyxy(pred_boxes[(size_t)b * NP + n]);
        Box gb = toxyxy(gt_boxes[b * GG + g]);
        float ov = neg_giou(p, gb);
        int label = gt_labels[b * GG + g];
        float s = g_scores_t[((size_t)b * CC + label) * NP + n];
        met = s * pow6(ov);
        inds = (float)(g + 1);
        lab = (float)label;
    }
    out[i] = inds;
    out[BS * NP + i] = lab;
    out[2 * BS * NP + i] = met;
}

// ---------------------------------------------------------------------------
extern "C" void kernel_launch(void* const* d_in, const int* in_sizes, int n_in,
                              void* d_out, int out_size) {
    const float*  logits     = (const float*)d_in[0];
    const float4* pred_boxes = (const float4*)d_in[1];
    const float4* gt_boxes   = (const float4*)d_in[2];
    const int*    gt_labels  = (const int*)d_in[3];
    float* out = (float*)d_out;

    dim3 tgrid(NP / 32, (CC + 31) / 32, BS);
    sig_transpose_kernel<<<tgrid, dim3(32, 8)>>>(logits);
    assign_kernel<<<BS * GG, NTH>>>(pred_boxes, gt_boxes, gt_labels);
    finalize_kernel<<<(BS * NP + 255) / 256, 256>>>(pred_boxes, gt_boxes, gt_labels, out);
}